// round 2
// baseline (speedup 1.0000x reference)
#include <cuda_runtime.h>
#include <math.h>

// Problem constants
#define Bn   2
#define HIDn 128
#define NVn  16
#define Hn   361
#define Wn   720
#define PADn 2
#define Hpn  (Hn + 2*PADn)      // 365
#define Wpn  (Wn + 2*PADn)      // 724
#define HWn  (Hn*Wn)            // 259920
#define ACO  (-0.75f)
#define TWOPI 6.28318530717958647692f

// Scratch (static device arrays; no runtime allocation)
__device__ float g_pad[(size_t)Bn*NVn*Hpn*Wpn];   // padded projected velocities
__device__ float g_y[(size_t)Bn*NVn*HWn];         // interp * dw_w + dw_b

// ---------------------------------------------------------------------------
// Kernel A: down projection (128 -> 16), write into padded interior
// thread per (b,h,w)
// ---------------------------------------------------------------------------
__global__ void kA_downproj(const float* __restrict__ x,
                            const float* __restrict__ down_w,
                            const float* __restrict__ down_b) {
    __shared__ float s_w[HIDn*NVn];   // layout [c][o] for contiguous o
    __shared__ float s_b[NVn];
    for (int i = threadIdx.x; i < HIDn*NVn; i += blockDim.x) {
        int o = i % NVn, c = i / NVn;
        s_w[c*NVn + o] = down_w[o*HIDn + c];
    }
    if (threadIdx.x < NVn) s_b[threadIdx.x] = down_b[threadIdx.x];
    __syncthreads();

    int idx = blockIdx.x * blockDim.x + threadIdx.x;
    if (idx >= Bn*HWn) return;
    int b = idx / HWn;
    int r = idx - b*HWn;
    int h = r / Wn;
    int w = r - h*Wn;

    float acc[NVn];
#pragma unroll
    for (int o = 0; o < NVn; o++) acc[o] = s_b[o];

    const float* xp = x + (size_t)b*HIDn*HWn + r;
#pragma unroll 4
    for (int c = 0; c < HIDn; c++) {
        float xv = xp[(size_t)c*HWn];
        const float4* w4 = reinterpret_cast<const float4*>(s_w + c*NVn);
#pragma unroll
        for (int j = 0; j < NVn/4; j++) {
            float4 wq = w4[j];
            acc[4*j+0] = fmaf(xv, wq.x, acc[4*j+0]);
            acc[4*j+1] = fmaf(xv, wq.y, acc[4*j+1]);
            acc[4*j+2] = fmaf(xv, wq.z, acc[4*j+2]);
            acc[4*j+3] = fmaf(xv, wq.w, acc[4*j+3]);
        }
    }
#pragma unroll
    for (int o = 0; o < NVn; o++) {
        g_pad[(((size_t)(b*NVn + o))*Hpn + (h + PADn))*Wpn + (w + PADn)] = acc[o];
    }
}

// ---------------------------------------------------------------------------
// Kernel B: pole-row fix on proj (mean over longitude, broadcast).
// Linear proj => equivalent to pole-fixing hidden first.
// one block per (plane, which_pole)
// ---------------------------------------------------------------------------
__global__ void kB_polefix_proj() {
    int plane = blockIdx.x >> 1;
    int which = blockIdx.x & 1;
    int hrow  = which ? (Hn - 1) : 0;
    float* row = g_pad + ((size_t)plane*Hpn + (hrow + PADn))*Wpn + PADn;

    __shared__ float s[256];
    float sum = 0.f;
    for (int w = threadIdx.x; w < Wn; w += 256) sum += row[w];
    s[threadIdx.x] = sum;
    __syncthreads();
    for (int st = 128; st > 0; st >>= 1) {
        if (threadIdx.x < st) s[threadIdx.x] += s[threadIdx.x + st];
        __syncthreads();
    }
    float mean = s[0] * (1.0f / (float)Wn);
    for (int w = threadIdx.x; w < Wn; w += 256) row[w] = mean;
}

// ---------------------------------------------------------------------------
// Kernel C: fill geo-cyclic halo.
//   top/bottom rows: reflected latitude with 180-deg longitude roll
//   left/right cols: cyclic longitude
// thread per padded cell; interior threads exit early.
// ---------------------------------------------------------------------------
__global__ void kC_halo() {
    int idx = blockIdx.x * blockDim.x + threadIdx.x;
    if (idx >= Bn*NVn*Hpn*Wpn) return;
    int plane = idx / (Hpn*Wpn);
    int rc = idx - plane*(Hpn*Wpn);
    int rrow = rc / Wpn;
    int pc = rc - rrow*Wpn;

    bool interior = (rrow >= PADn) && (rrow < PADn + Hn) &&
                    (pc >= PADn) && (pc < PADn + Wn);
    if (interior) return;

    // map padded col -> pre-longitude-pad col
    int cj;
    if (pc < PADn)            cj = Wn - PADn + pc;
    else if (pc >= PADn + Wn) cj = pc - PADn - Wn;
    else                      cj = pc - PADn;

    int sr;
    if (rrow < PADn) {                       // top: flip + roll W/2
        sr = PADn - 1 - rrow;
        cj = (cj + Wn/2) % Wn;
    } else if (rrow >= PADn + Hn) {          // bottom: flip + roll W/2
        int i = rrow - (PADn + Hn);
        sr = Hn - 1 - i;
        cj = (cj + Wn/2) % Wn;
    } else {
        sr = rrow - PADn;
    }
    g_pad[(size_t)plane*Hpn*Wpn + rc] =
        g_pad[((size_t)plane*Hpn + (sr + PADn))*Wpn + (cj + PADn)];
}

// ---------------------------------------------------------------------------
// Kernel D1: departure point + bicubic sample + depthwise scale.
// thread per (b,v,h,w)
// ---------------------------------------------------------------------------
__global__ void kD1_sample(const float* __restrict__ U,
                           const float* __restrict__ Vf,
                           const float* __restrict__ dtp,
                           const float* __restrict__ latg,
                           const float* __restrict__ lonp,
                           const float* __restrict__ dww,
                           const float* __restrict__ dwb) {
    int idx = blockIdx.x * blockDim.x + threadIdx.x;
    if (idx >= Bn*NVn*HWn) return;
    int plane = idx / HWn;
    int r = idx - plane*HWn;
    int v = plane % NVn;

    float dt = __ldg(dtp);
    float minLat = __ldg(latg);
    float maxLat = __ldg(latg + (size_t)(Hn-1)*Wn);
    float minLon = __ldg(lonp);
    float maxLon = __ldg(lonp + (Wn-1));
    float dLat = maxLat - minLat;
    float dLon = maxLon - minLon;

    float lg = __ldg(latg + r);
    float lo = __ldg(lonp + r);
    float slg, clg;
    sincosf(lg, &slg, &clg);

    float uu = U[idx];
    float vv = Vf[idx];
    float lon_pr = -uu * dt;
    float lat_pr = -vv * dt;
    float slp, clp, sln, cln;
    sincosf(lat_pr, &slp, &clp);
    sincosf(lon_pr, &sln, &cln);

    float sin_lat = slp*clg + clp*cln*slg;
    sin_lat = fminf(fmaxf(sin_lat, -1.0f + 1e-7f), 1.0f - 1e-7f);
    float lat_dep = asinf(sin_lat);
    float num = clp * sln;
    float den = clp*cln*clg - slp*slg;
    float lon_dep = lo + atan2f(num, den);
    float a = lon_dep + TWOPI;
    lon_dep = a - floorf(a * (1.0f/TWOPI)) * TWOPI;   // jnp.remainder(a, 2pi)

    float pix_x = (lon_dep - minLon) / dLon * (float)(Wn - 1);
    float pix_y = (lat_dep - minLat) / dLat * (float)(Hn - 1);
    // normalize/unnormalize round trip (align_corners=True), matches reference fp path
    float gx = 2.0f*((pix_x + (float)PADn)/(float)(Wpn - 1)) - 1.0f;
    float gy = 2.0f*((pix_y + (float)PADn)/(float)(Hpn - 1)) - 1.0f;
    float ix = (gx + 1.0f)*0.5f*(float)(Wpn - 1);
    float iy = (gy + 1.0f)*0.5f*(float)(Hpn - 1);

    float x0f = floorf(ix), y0f = floorf(iy);
    float tx = ix - x0f, ty = iy - y0f;
    int x0 = (int)x0f, y0 = (int)y0f;

    float wx[4], wy[4];
    {
        float t = tx, t1 = t + 1.0f, t2 = 1.0f - t, t3 = 2.0f - t;
        wx[0] = ((ACO*t1 - 5.0f*ACO)*t1 + 8.0f*ACO)*t1 - 4.0f*ACO;
        wx[1] = ((ACO + 2.0f)*t - (ACO + 3.0f))*t*t + 1.0f;
        wx[2] = ((ACO + 2.0f)*t2 - (ACO + 3.0f))*t2*t2 + 1.0f;
        wx[3] = ((ACO*t3 - 5.0f*ACO)*t3 + 8.0f*ACO)*t3 - 4.0f*ACO;
    }
    {
        float t = ty, t1 = t + 1.0f, t2 = 1.0f - t, t3 = 2.0f - t;
        wy[0] = ((ACO*t1 - 5.0f*ACO)*t1 + 8.0f*ACO)*t1 - 4.0f*ACO;
        wy[1] = ((ACO + 2.0f)*t - (ACO + 3.0f))*t*t + 1.0f;
        wy[2] = ((ACO + 2.0f)*t2 - (ACO + 3.0f))*t2*t2 + 1.0f;
        wy[3] = ((ACO*t3 - 5.0f*ACO)*t3 + 8.0f*ACO)*t3 - 4.0f*ACO;
    }

    const float* pp = g_pad + (size_t)plane*Hpn*Wpn;
    float acc = 0.0f;
#pragma unroll
    for (int dy = 0; dy < 4; dy++) {
        int yy = y0 + dy - 1;
        if (yy < 0 || yy >= Hpn) continue;
        const float* rp = pp + (size_t)yy*Wpn;
        float rs = 0.0f;
#pragma unroll
        for (int dx = 0; dx < 4; dx++) {
            int xx = x0 + dx - 1;
            if (xx >= 0 && xx < Wpn) rs = fmaf(rp[xx], wx[dx], rs);
        }
        acc = fmaf(rs, wy[dy], acc);
    }
    g_y[idx] = fmaf(acc, __ldg(dww + v), __ldg(dwb + v));
}

// ---------------------------------------------------------------------------
// Kernel D2: up projection (16 -> 128). thread per (b,h,w)
// ---------------------------------------------------------------------------
__global__ void kD2_upproj(const float* __restrict__ upw,
                           const float* __restrict__ upb,
                           float* __restrict__ out) {
    __shared__ float s_w[HIDn*NVn];
    __shared__ float s_b[HIDn];
    for (int i = threadIdx.x; i < HIDn*NVn; i += blockDim.x) s_w[i] = upw[i];
    for (int i = threadIdx.x; i < HIDn; i += blockDim.x) s_b[i] = upb[i];
    __syncthreads();

    int idx = blockIdx.x * blockDim.x + threadIdx.x;
    if (idx >= Bn*HWn) return;
    int b = idx / HWn;
    int r = idx - b*HWn;

    float yv[NVn];
    const float* yp = g_y + (size_t)b*NVn*HWn + r;
#pragma unroll
    for (int v = 0; v < NVn; v++) yv[v] = yp[(size_t)v*HWn];

    float* op = out + (size_t)b*HIDn*HWn + r;
#pragma unroll 8
    for (int o = 0; o < HIDn; o++) {
        float acc = s_b[o];
        const float4* w4 = reinterpret_cast<const float4*>(s_w + o*NVn);
#pragma unroll
        for (int j = 0; j < NVn/4; j++) {
            float4 wq = w4[j];
            acc = fmaf(yv[4*j+0], wq.x, acc);
            acc = fmaf(yv[4*j+1], wq.y, acc);
            acc = fmaf(yv[4*j+2], wq.z, acc);
            acc = fmaf(yv[4*j+3], wq.w, acc);
        }
        op[(size_t)o*HWn] = acc;
    }
}

// ---------------------------------------------------------------------------
// Kernel E: pole-row fix on output. one block per (b*HID + o, which_pole)
// ---------------------------------------------------------------------------
__global__ void kE_polefix_out(float* __restrict__ out) {
    int bo = blockIdx.x >> 1;
    int which = blockIdx.x & 1;
    float* row = out + (size_t)bo*HWn + (which ? (size_t)(Hn-1)*Wn : 0);

    __shared__ float s[256];
    float sum = 0.f;
    for (int w = threadIdx.x; w < Wn; w += 256) sum += row[w];
    s[threadIdx.x] = sum;
    __syncthreads();
    for (int st = 128; st > 0; st >>= 1) {
        if (threadIdx.x < st) s[threadIdx.x] += s[threadIdx.x + st];
        __syncthreads();
    }
    float mean = s[0] * (1.0f / (float)Wn);
    for (int w = threadIdx.x; w < Wn; w += 256) row[w] = mean;
}

// ---------------------------------------------------------------------------
extern "C" void kernel_launch(void* const* d_in, const int* in_sizes, int n_in,
                              void* d_out, int out_size) {
    const float* hidden = (const float*)d_in[0];
    const float* U      = (const float*)d_in[1];
    const float* V      = (const float*)d_in[2];
    const float* dt     = (const float*)d_in[3];
    const float* latg   = (const float*)d_in[4];
    const float* lonog  = (const float*)d_in[5];
    const float* down_w = (const float*)d_in[6];
    const float* down_b = (const float*)d_in[7];
    const float* dw_w   = (const float*)d_in[8];
    const float* dw_b   = (const float*)d_in[9];
    const float* up_w   = (const float*)d_in[10];
    const float* up_b   = (const float*)d_in[11];
    float* out = (float*)d_out;

    int nPts = Bn*HWn;                       // 519840
    kA_downproj<<<(nPts + 255)/256, 256>>>(hidden, down_w, down_b);
    kB_polefix_proj<<<Bn*NVn*2, 256>>>();
    int nPad = Bn*NVn*Hpn*Wpn;               // 8,456,320
    kC_halo<<<(nPad + 255)/256, 256>>>();
    int nSamp = Bn*NVn*HWn;                  // 8,317,440
    kD1_sample<<<(nSamp + 255)/256, 256>>>(U, V, dt, latg, lonog, dw_w, dw_b);
    kD2_upproj<<<(nPts + 255)/256, 256>>>(up_w, up_b, out);
    kE_polefix_out<<<Bn*HIDn*2, 256>>>(out);
}

// round 3
// speedup vs baseline: 1.0268x; 1.0268x over previous
#include <cuda_runtime.h>
#include <math.h>

// Problem constants
#define Bn   2
#define HIDn 128
#define NVn  16
#define Hn   361
#define Wn   720
#define PADn 2
#define Hpn  (Hn + 2*PADn)      // 365
#define Wpn  (Wn + 2*PADn)      // 724
#define HWn  (Hn*Wn)            // 259920
#define ACO  (-0.75f)
#define TWOPI 6.28318530717958647692f

typedef unsigned long long ull;

// Scratch (static device arrays; no runtime allocation)
__device__ float g_pad[(size_t)Bn*NVn*Hpn*Wpn];   // padded projected velocities
__device__ float g_y[(size_t)Bn*NVn*HWn];         // interp * dw_w + dw_b
__device__ float g_slat[Hn];
__device__ float g_clat[Hn];

// ---- packed fp32x2 helpers ------------------------------------------------
__device__ __forceinline__ ull pk2(float a, float b) {
    ull r; asm("mov.b64 %0, {%1, %2};" : "=l"(r) : "f"(a), "f"(b)); return r;
}
__device__ __forceinline__ float2 upk2(ull v) {
    float2 r; asm("mov.b64 {%0, %1}, %2;" : "=f"(r.x), "=f"(r.y) : "l"(v)); return r;
}
__device__ __forceinline__ ull ffma2(ull a, ull b, ull c) {
    ull d; asm("fma.rn.f32x2 %0, %1, %2, %3;" : "=l"(d) : "l"(a), "l"(b), "l"(c)); return d;
}

// ---------------------------------------------------------------------------
// Kernel T: per-latitude-row sincos table (361 entries)
// ---------------------------------------------------------------------------
__global__ void kT_tables(const float* __restrict__ latg) {
    int h = blockIdx.x * blockDim.x + threadIdx.x;
    if (h < Hn) {
        float s, c;
        sincosf(latg[(size_t)h * Wn], &s, &c);
        g_slat[h] = s;
        g_clat[h] = c;
    }
}

// ---------------------------------------------------------------------------
// Kernel A: down projection (128 -> 16), 2 adjacent pixels per thread via
// packed fp32x2 FMA. Writes into padded interior.
// ---------------------------------------------------------------------------
__global__ void kA_downproj(const float* __restrict__ x,
                            const float* __restrict__ down_w,
                            const float* __restrict__ down_b) {
    __shared__ ull s_w2[HIDn*NVn];   // [c][o], weight broadcast-packed
    __shared__ float s_b[NVn];
    for (int i = threadIdx.x; i < HIDn*NVn; i += blockDim.x) {
        int o = i % NVn, c = i / NVn;
        float wv = down_w[o*HIDn + c];
        s_w2[c*NVn + o] = pk2(wv, wv);
    }
    if (threadIdx.x < NVn) s_b[threadIdx.x] = down_b[threadIdx.x];
    __syncthreads();

    int idx = blockIdx.x * blockDim.x + threadIdx.x;   // pair index
    if (idx >= Bn*(HWn/2)) return;
    int b = idx / (HWn/2);
    int r = (idx - b*(HWn/2)) * 2;     // even; pairs never straddle rows (Wn even)
    int h = r / Wn;
    int w = r - h*Wn;

    ull acc[NVn];
#pragma unroll
    for (int o = 0; o < NVn; o++) acc[o] = pk2(s_b[o], s_b[o]);

    const float* xp = x + (size_t)b*HIDn*HWn + r;
#pragma unroll 4
    for (int c = 0; c < HIDn; c++) {
        ull xv = *reinterpret_cast<const ull*>(xp + (size_t)c*HWn);
        const ull* wr = s_w2 + c*NVn;
#pragma unroll
        for (int o = 0; o < NVn; o++) acc[o] = ffma2(xv, wr[o], acc[o]);
    }
#pragma unroll
    for (int o = 0; o < NVn; o++) {
        *reinterpret_cast<ull*>(
            &g_pad[(((size_t)(b*NVn + o))*Hpn + (h + PADn))*Wpn + (w + PADn)]) = acc[o];
    }
}

// ---------------------------------------------------------------------------
// Kernel B: pole-row fix on proj (mean over longitude, broadcast).
// ---------------------------------------------------------------------------
__global__ void kB_polefix_proj() {
    int plane = blockIdx.x >> 1;
    int which = blockIdx.x & 1;
    int hrow  = which ? (Hn - 1) : 0;
    float* row = g_pad + ((size_t)plane*Hpn + (hrow + PADn))*Wpn + PADn;

    __shared__ float s[256];
    float sum = 0.f;
    for (int w = threadIdx.x; w < Wn; w += 256) sum += row[w];
    s[threadIdx.x] = sum;
    __syncthreads();
    for (int st = 128; st > 0; st >>= 1) {
        if (threadIdx.x < st) s[threadIdx.x] += s[threadIdx.x + st];
        __syncthreads();
    }
    float mean = s[0] * (1.0f / (float)Wn);
    for (int w = threadIdx.x; w < Wn; w += 256) row[w] = mean;
}

// ---------------------------------------------------------------------------
// Kernel C: fill geo-cyclic halo.
// ---------------------------------------------------------------------------
__global__ void kC_halo() {
    int idx = blockIdx.x * blockDim.x + threadIdx.x;
    if (idx >= Bn*NVn*Hpn*Wpn) return;
    int plane = idx / (Hpn*Wpn);
    int rc = idx - plane*(Hpn*Wpn);
    int rrow = rc / Wpn;
    int pc = rc - rrow*Wpn;

    bool interior = (rrow >= PADn) && (rrow < PADn + Hn) &&
                    (pc >= PADn) && (pc < PADn + Wn);
    if (interior) return;

    int cj;
    if (pc < PADn)            cj = Wn - PADn + pc;
    else if (pc >= PADn + Wn) cj = pc - PADn - Wn;
    else                      cj = pc - PADn;

    int sr;
    if (rrow < PADn) {
        sr = PADn - 1 - rrow;
        cj = (cj + Wn/2) % Wn;
    } else if (rrow >= PADn + Hn) {
        int i = rrow - (PADn + Hn);
        sr = Hn - 1 - i;
        cj = (cj + Wn/2) % Wn;
    } else {
        sr = rrow - PADn;
    }
    g_pad[(size_t)plane*Hpn*Wpn + rc] =
        g_pad[((size_t)plane*Hpn + (sr + PADn))*Wpn + (cj + PADn)];
}

// ---------------------------------------------------------------------------
// small-angle sin/cos (|x| < ~0.1): abs error < 2e-9
// ---------------------------------------------------------------------------
__device__ __forceinline__ float sin_sm(float x) {
    float x2 = x*x;
    return x * fmaf(x2, fmaf(x2, 8.3333333e-3f, -1.6666667e-1f), 1.0f);
}
__device__ __forceinline__ float cos_sm(float x) {
    float x2 = x*x;
    return fmaf(x2, fmaf(x2, 4.1666667e-2f, -0.5f), 1.0f);
}

// ---------------------------------------------------------------------------
// Kernel D1: departure point + bicubic sample + depthwise scale.
// grid: (3, Bn*NVn*Hn), block 256; thread = one (plane, h, w)
// All 16 taps proven in-bounds -> no predicates.
// ---------------------------------------------------------------------------
__global__ void kD1_sample(const float* __restrict__ U,
                           const float* __restrict__ Vf,
                           const float* __restrict__ dtp,
                           const float* __restrict__ latg,
                           const float* __restrict__ lonp,
                           const float* __restrict__ dww,
                           const float* __restrict__ dwb) {
    int w = blockIdx.x * blockDim.x + threadIdx.x;
    if (w >= Wn) return;
    int py = blockIdx.y;
    int plane = py / Hn;
    int h = py - plane*Hn;
    int v = plane & (NVn - 1);

    float dt = __ldg(dtp);
    float minLat = __ldg(latg);
    float maxLat = __ldg(latg + (size_t)(Hn-1)*Wn);
    float minLon = __ldg(lonp);
    float maxLon = __ldg(lonp + (Wn-1));
    float dLat = maxLat - minLat;
    float dLon = maxLon - minLon;

    float slg = g_slat[h];
    float clg = g_clat[h];
    float lo  = __ldg(lonp + w);

    size_t base = (size_t)plane*HWn + (size_t)h*Wn + w;
    float uu = U[base];
    float vv = Vf[base];
    float lon_pr = -uu * dt;
    float lat_pr = -vv * dt;
    float slp = sin_sm(lat_pr), clp = cos_sm(lat_pr);
    float sln = sin_sm(lon_pr), cln = cos_sm(lon_pr);

    float sin_lat = fmaf(slp, clg, clp*cln*slg);
    sin_lat = fminf(fmaxf(sin_lat, -1.0f + 1e-7f), 1.0f - 1e-7f);
    float lat_dep = asinf(sin_lat);
    float num = clp * sln;
    float den = clp*cln*clg - slp*slg;
    float lon_dep = lo + atan2f(num, den);
    float a = lon_dep + TWOPI;
    lon_dep = a - floorf(a * (1.0f/TWOPI)) * TWOPI;   // remainder(a, 2pi)

    float pix_x = (lon_dep - minLon) / dLon * (float)(Wn - 1);
    float pix_y = (lat_dep - minLat) / dLat * (float)(Hn - 1);
    // normalize/unnormalize round trip (align_corners=True), matches reference fp path
    float gx = 2.0f*((pix_x + (float)PADn)/(float)(Wpn - 1)) - 1.0f;
    float gy = 2.0f*((pix_y + (float)PADn)/(float)(Hpn - 1)) - 1.0f;
    float ix = (gx + 1.0f)*0.5f*(float)(Wpn - 1);
    float iy = (gy + 1.0f)*0.5f*(float)(Hpn - 1);

    float x0f = floorf(ix), y0f = floorf(iy);
    float tx = ix - x0f, ty = iy - y0f;
    int x0 = (int)x0f, y0 = (int)y0f;

    float wx0, wx1, wx2, wx3, wy0, wy1, wy2, wy3;
    {
        float t = tx, t1 = t + 1.0f, t2 = 1.0f - t, t3 = 2.0f - t;
        wx0 = ((ACO*t1 - 5.0f*ACO)*t1 + 8.0f*ACO)*t1 - 4.0f*ACO;
        wx1 = ((ACO + 2.0f)*t - (ACO + 3.0f))*t*t + 1.0f;
        wx2 = ((ACO + 2.0f)*t2 - (ACO + 3.0f))*t2*t2 + 1.0f;
        wx3 = ((ACO*t3 - 5.0f*ACO)*t3 + 8.0f*ACO)*t3 - 4.0f*ACO;
    }
    {
        float t = ty, t1 = t + 1.0f, t2 = 1.0f - t, t3 = 2.0f - t;
        wy0 = ((ACO*t1 - 5.0f*ACO)*t1 + 8.0f*ACO)*t1 - 4.0f*ACO;
        wy1 = ((ACO + 2.0f)*t - (ACO + 3.0f))*t*t + 1.0f;
        wy2 = ((ACO + 2.0f)*t2 - (ACO + 3.0f))*t2*t2 + 1.0f;
        wy3 = ((ACO*t3 - 5.0f*ACO)*t3 + 8.0f*ACO)*t3 - 4.0f*ACO;
    }

    const float* rp = g_pad + (size_t)plane*Hpn*Wpn + (size_t)(y0-1)*Wpn + (x0-1);
    float r0 = fmaf(rp[3], wx3, fmaf(rp[2], wx2, fmaf(rp[1], wx1, rp[0]*wx0)));
    rp += Wpn;
    float r1 = fmaf(rp[3], wx3, fmaf(rp[2], wx2, fmaf(rp[1], wx1, rp[0]*wx0)));
    rp += Wpn;
    float r2 = fmaf(rp[3], wx3, fmaf(rp[2], wx2, fmaf(rp[1], wx1, rp[0]*wx0)));
    rp += Wpn;
    float r3 = fmaf(rp[3], wx3, fmaf(rp[2], wx2, fmaf(rp[1], wx1, rp[0]*wx0)));
    float acc = fmaf(r3, wy3, fmaf(r2, wy2, fmaf(r1, wy1, r0*wy0)));

    g_y[base] = fmaf(acc, __ldg(dww + v), __ldg(dwb + v));
}

// ---------------------------------------------------------------------------
// Kernel D2: up projection (16 -> 128), 2 pixels/thread via packed fp32x2.
// ---------------------------------------------------------------------------
__global__ void kD2_upproj(const float* __restrict__ upw,
                           const float* __restrict__ upb,
                           float* __restrict__ out) {
    __shared__ ull s_w2[HIDn*NVn];   // [o][v], broadcast-packed
    __shared__ float s_b[HIDn];
    for (int i = threadIdx.x; i < HIDn*NVn; i += blockDim.x) {
        float wv = upw[i];
        s_w2[i] = pk2(wv, wv);
    }
    for (int i = threadIdx.x; i < HIDn; i += blockDim.x) s_b[i] = upb[i];
    __syncthreads();

    int idx = blockIdx.x * blockDim.x + threadIdx.x;   // pair index
    if (idx >= Bn*(HWn/2)) return;
    int b = idx / (HWn/2);
    int r = (idx - b*(HWn/2)) * 2;

    ull yv[NVn];
    const float* yp = g_y + (size_t)b*NVn*HWn + r;
#pragma unroll
    for (int vq = 0; vq < NVn; vq++)
        yv[vq] = *reinterpret_cast<const ull*>(yp + (size_t)vq*HWn);

    float* op = out + (size_t)b*HIDn*HWn + r;
#pragma unroll 8
    for (int o = 0; o < HIDn; o++) {
        ull acc = pk2(s_b[o], s_b[o]);
        const ull* wr = s_w2 + o*NVn;
#pragma unroll
        for (int vq = 0; vq < NVn; vq++) acc = ffma2(yv[vq], wr[vq], acc);
        *reinterpret_cast<ull*>(op + (size_t)o*HWn) = acc;
    }
}

// ---------------------------------------------------------------------------
// Kernel E: pole-row fix on output.
// ---------------------------------------------------------------------------
__global__ void kE_polefix_out(float* __restrict__ out) {
    int bo = blockIdx.x >> 1;
    int which = blockIdx.x & 1;
    float* row = out + (size_t)bo*HWn + (which ? (size_t)(Hn-1)*Wn : 0);

    __shared__ float s[256];
    float sum = 0.f;
    for (int w = threadIdx.x; w < Wn; w += 256) sum += row[w];
    s[threadIdx.x] = sum;
    __syncthreads();
    for (int st = 128; st > 0; st >>= 1) {
        if (threadIdx.x < st) s[threadIdx.x] += s[threadIdx.x + st];
        __syncthreads();
    }
    float mean = s[0] * (1.0f / (float)Wn);
    for (int w = threadIdx.x; w < Wn; w += 256) row[w] = mean;
}

// ---------------------------------------------------------------------------
extern "C" void kernel_launch(void* const* d_in, const int* in_sizes, int n_in,
                              void* d_out, int out_size) {
    const float* hidden = (const float*)d_in[0];
    const float* U      = (const float*)d_in[1];
    const float* V      = (const float*)d_in[2];
    const float* dt     = (const float*)d_in[3];
    const float* latg   = (const float*)d_in[4];
    const float* lonog  = (const float*)d_in[5];
    const float* down_w = (const float*)d_in[6];
    const float* down_b = (const float*)d_in[7];
    const float* dw_w   = (const float*)d_in[8];
    const float* dw_b   = (const float*)d_in[9];
    const float* up_w   = (const float*)d_in[10];
    const float* up_b   = (const float*)d_in[11];
    float* out = (float*)d_out;

    kT_tables<<<2, 256>>>(latg);

    int nPairs = Bn*(HWn/2);                 // 259920
    kA_downproj<<<(nPairs + 255)/256, 256>>>(hidden, down_w, down_b);
    kB_polefix_proj<<<Bn*NVn*2, 256>>>();
    int nPad = Bn*NVn*Hpn*Wpn;               // 8,456,320
    kC_halo<<<(nPad + 255)/256, 256>>>();
    dim3 gD1((Wn + 255)/256, Bn*NVn*Hn);
    kD1_sample<<<gD1, 256>>>(U, V, dt, latg, lonog, dw_w, dw_b);
    kD2_upproj<<<(nPairs + 255)/256, 256>>>(up_w, up_b, out);
    kE_polefix_out<<<Bn*HIDn*2, 256>>>(out);
}

// round 4
// speedup vs baseline: 1.0527x; 1.0252x over previous
#include <cuda_runtime.h>
#include <math.h>

// Problem constants
#define Bn   2
#define HIDn 128
#define NVn  16
#define Hn   361
#define Wn   720
#define PADn 2
#define Hpn  (Hn + 2*PADn)      // 365
#define Wpn  (Wn + 2*PADn)      // 724
#define HWn  (Hn*Wn)            // 259920
#define ACO  (-0.75f)
#define TWOPI 6.28318530717958647692f

typedef unsigned long long ull;

// Scratch (static device arrays; no runtime allocation)
__device__ float g_pad[(size_t)Bn*NVn*Hpn*Wpn];   // padded projected velocities
__device__ float g_slat[Hn];
__device__ float g_clat[Hn];

// ---- packed fp32x2 helpers ------------------------------------------------
__device__ __forceinline__ ull pk2(float a, float b) {
    ull r; asm("mov.b64 %0, {%1, %2};" : "=l"(r) : "f"(a), "f"(b)); return r;
}
__device__ __forceinline__ ull ffma2(ull a, ull b, ull c) {
    ull d; asm("fma.rn.f32x2 %0, %1, %2, %3;" : "=l"(d) : "l"(a), "l"(b), "l"(c)); return d;
}

// ---------------------------------------------------------------------------
// Kernel T: per-latitude-row sincos table (361 entries)
// ---------------------------------------------------------------------------
__global__ void kT_tables(const float* __restrict__ latg) {
    int h = blockIdx.x * blockDim.x + threadIdx.x;
    if (h < Hn) {
        float s, c;
        sincosf(latg[(size_t)h * Wn], &s, &c);
        g_slat[h] = s;
        g_clat[h] = c;
    }
}

// ---------------------------------------------------------------------------
// Kernel A: down projection (128 -> 16), 2 adjacent pixels per thread via
// packed fp32x2 FMA. Writes into padded interior.
// ---------------------------------------------------------------------------
__global__ void kA_downproj(const float* __restrict__ x,
                            const float* __restrict__ down_w,
                            const float* __restrict__ down_b) {
    __shared__ ull s_w2[HIDn*NVn];   // [c][o], weight broadcast-packed
    __shared__ float s_b[NVn];
    for (int i = threadIdx.x; i < HIDn*NVn; i += blockDim.x) {
        int o = i % NVn, c = i / NVn;
        float wv = down_w[o*HIDn + c];
        s_w2[c*NVn + o] = pk2(wv, wv);
    }
    if (threadIdx.x < NVn) s_b[threadIdx.x] = down_b[threadIdx.x];
    __syncthreads();

    int idx = blockIdx.x * blockDim.x + threadIdx.x;   // pair index
    if (idx >= Bn*(HWn/2)) return;
    int b = idx / (HWn/2);
    int r = (idx - b*(HWn/2)) * 2;     // even; pairs never straddle rows (Wn even)
    int h = r / Wn;
    int w = r - h*Wn;

    ull acc[NVn];
#pragma unroll
    for (int o = 0; o < NVn; o++) acc[o] = pk2(s_b[o], s_b[o]);

    const float* xp = x + (size_t)b*HIDn*HWn + r;
#pragma unroll 4
    for (int c = 0; c < HIDn; c++) {
        ull xv = *reinterpret_cast<const ull*>(xp + (size_t)c*HWn);
        const ull* wr = s_w2 + c*NVn;
#pragma unroll
        for (int o = 0; o < NVn; o++) acc[o] = ffma2(xv, wr[o], acc[o]);
    }
#pragma unroll
    for (int o = 0; o < NVn; o++) {
        *reinterpret_cast<ull*>(
            &g_pad[(((size_t)(b*NVn + o))*Hpn + (h + PADn))*Wpn + (w + PADn)]) = acc[o];
    }
}

// ---------------------------------------------------------------------------
// Kernel B: pole-row fix on proj (mean over longitude, broadcast).
// ---------------------------------------------------------------------------
__global__ void kB_polefix_proj() {
    int plane = blockIdx.x >> 1;
    int which = blockIdx.x & 1;
    int hrow  = which ? (Hn - 1) : 0;
    float* row = g_pad + ((size_t)plane*Hpn + (hrow + PADn))*Wpn + PADn;

    __shared__ float s[256];
    float sum = 0.f;
    for (int w = threadIdx.x; w < Wn; w += 256) sum += row[w];
    s[threadIdx.x] = sum;
    __syncthreads();
    for (int st = 128; st > 0; st >>= 1) {
        if (threadIdx.x < st) s[threadIdx.x] += s[threadIdx.x + st];
        __syncthreads();
    }
    float mean = s[0] * (1.0f / (float)Wn);
    for (int w = threadIdx.x; w < Wn; w += 256) row[w] = mean;
}

// ---------------------------------------------------------------------------
// Kernel C: fill geo-cyclic halo — halo cells only.
// Per plane: 4 full-width rows (2 top + 2 bottom) + 361 rows x 4 side cols
//          = 4*Wpn + Hn*4 = 4340 cells. Total 32*4340 = 138,880 threads.
// ---------------------------------------------------------------------------
#define HALO_PER_PLANE (4*Wpn + Hn*4)
__global__ void kC_halo() {
    int idx = blockIdx.x * blockDim.x + threadIdx.x;
    if (idx >= Bn*NVn*HALO_PER_PLANE) return;
    int plane = idx / HALO_PER_PLANE;
    int i = idx - plane*HALO_PER_PLANE;

    int rrow, pc;
    if (i < 2*Wpn) {                      // top 2 rows
        rrow = i / Wpn;
        pc = i - rrow*Wpn;
    } else if (i < 4*Wpn) {               // bottom 2 rows
        int j = i - 2*Wpn;
        rrow = Hpn - 2 + j / Wpn;
        pc = j - (j/Wpn)*Wpn;
    } else {                              // side columns of middle rows
        int j = i - 4*Wpn;
        rrow = PADn + (j >> 2);
        int k = j & 3;
        pc = (k < 2) ? k : (Wpn - 4 + k);
    }

    // map padded col -> pre-longitude-pad col
    int cj;
    if (pc < PADn)            cj = Wn - PADn + pc;
    else if (pc >= PADn + Wn) cj = pc - PADn - Wn;
    else                      cj = pc - PADn;

    int sr;
    if (rrow < PADn) {                    // top: flip + roll W/2
        sr = PADn - 1 - rrow;
        cj = (cj + Wn/2) % Wn;
    } else if (rrow >= PADn + Hn) {       // bottom: flip + roll W/2
        int t = rrow - (PADn + Hn);
        sr = Hn - 1 - t;
        cj = (cj + Wn/2) % Wn;
    } else {
        sr = rrow - PADn;
    }
    g_pad[((size_t)plane*Hpn + rrow)*Wpn + pc] =
        g_pad[((size_t)plane*Hpn + (sr + PADn))*Wpn + (cj + PADn)];
}

// ---------------------------------------------------------------------------
// small-angle sin/cos (|x| < ~0.1): abs error < 2e-9
// ---------------------------------------------------------------------------
__device__ __forceinline__ float sin_sm(float x) {
    float x2 = x*x;
    return x * fmaf(x2, fmaf(x2, 8.3333333e-3f, -1.6666667e-1f), 1.0f);
}
__device__ __forceinline__ float cos_sm(float x) {
    float x2 = x*x;
    return fmaf(x2, fmaf(x2, 4.1666667e-2f, -0.5f), 1.0f);
}

// one departure-point bicubic sample (all taps proven in-bounds)
__device__ __forceinline__ float sample_one(
        const float* __restrict__ pp, float uu, float vv, float dt,
        float slg, float clg, float lo,
        float minLat, float dLatInv, float minLon, float dLonInv) {
    float lon_pr = -uu * dt;
    float lat_pr = -vv * dt;
    float slp = sin_sm(lat_pr), clp = cos_sm(lat_pr);
    float sln = sin_sm(lon_pr), cln = cos_sm(lon_pr);

    float sin_lat = fmaf(slp, clg, clp*cln*slg);
    sin_lat = fminf(fmaxf(sin_lat, -1.0f + 1e-7f), 1.0f - 1e-7f);
    float lat_dep = asinf(sin_lat);
    float num = clp * sln;
    float den = clp*cln*clg - slp*slg;
    float lon_dep = lo + atan2f(num, den);
    float a = lon_dep + TWOPI;
    lon_dep = a - floorf(a * (1.0f/TWOPI)) * TWOPI;   // remainder(a, 2pi)

    float pix_x = (lon_dep - minLon) * dLonInv * (float)(Wn - 1);
    float pix_y = (lat_dep - minLat) * dLatInv * (float)(Hn - 1);
    // normalize/unnormalize round trip (align_corners=True), matches reference fp path
    float gx = 2.0f*((pix_x + (float)PADn)/(float)(Wpn - 1)) - 1.0f;
    float gy = 2.0f*((pix_y + (float)PADn)/(float)(Hpn - 1)) - 1.0f;
    float ix = (gx + 1.0f)*0.5f*(float)(Wpn - 1);
    float iy = (gy + 1.0f)*0.5f*(float)(Hpn - 1);

    float x0f = floorf(ix), y0f = floorf(iy);
    float tx = ix - x0f, ty = iy - y0f;
    int x0 = (int)x0f, y0 = (int)y0f;

    float wx0, wx1, wx2, wx3, wy0, wy1, wy2, wy3;
    {
        float t = tx, t1 = t + 1.0f, t2 = 1.0f - t, t3 = 2.0f - t;
        wx0 = ((ACO*t1 - 5.0f*ACO)*t1 + 8.0f*ACO)*t1 - 4.0f*ACO;
        wx1 = ((ACO + 2.0f)*t - (ACO + 3.0f))*t*t + 1.0f;
        wx2 = ((ACO + 2.0f)*t2 - (ACO + 3.0f))*t2*t2 + 1.0f;
        wx3 = ((ACO*t3 - 5.0f*ACO)*t3 + 8.0f*ACO)*t3 - 4.0f*ACO;
    }
    {
        float t = ty, t1 = t + 1.0f, t2 = 1.0f - t, t3 = 2.0f - t;
        wy0 = ((ACO*t1 - 5.0f*ACO)*t1 + 8.0f*ACO)*t1 - 4.0f*ACO;
        wy1 = ((ACO + 2.0f)*t - (ACO + 3.0f))*t*t + 1.0f;
        wy2 = ((ACO + 2.0f)*t2 - (ACO + 3.0f))*t2*t2 + 1.0f;
        wy3 = ((ACO*t3 - 5.0f*ACO)*t3 + 8.0f*ACO)*t3 - 4.0f*ACO;
    }

    const float* rp = pp + (size_t)(y0-1)*Wpn + (x0-1);
    float r0 = fmaf(rp[3], wx3, fmaf(rp[2], wx2, fmaf(rp[1], wx1, rp[0]*wx0)));
    rp += Wpn;
    float r1 = fmaf(rp[3], wx3, fmaf(rp[2], wx2, fmaf(rp[1], wx1, rp[0]*wx0)));
    rp += Wpn;
    float r2 = fmaf(rp[3], wx3, fmaf(rp[2], wx2, fmaf(rp[1], wx1, rp[0]*wx0)));
    rp += Wpn;
    float r3 = fmaf(rp[3], wx3, fmaf(rp[2], wx2, fmaf(rp[1], wx1, rp[0]*wx0)));
    return fmaf(r3, wy3, fmaf(r2, wy2, fmaf(r1, wy1, r0*wy0)));
}

// ---------------------------------------------------------------------------
// Kernel F (fused D1+D2): per pixel-pair, compute all 16 velocity samples,
// depthwise scale, then 16->128 up projection, write out. No g_y round trip.
// ---------------------------------------------------------------------------
__global__ void __launch_bounds__(256, 2)
kF_sample_upproj(const float* __restrict__ U,
                 const float* __restrict__ Vf,
                 const float* __restrict__ dtp,
                 const float* __restrict__ latg,
                 const float* __restrict__ lonp,
                 const float* __restrict__ dww,
                 const float* __restrict__ dwb,
                 const float* __restrict__ upw,
                 const float* __restrict__ upb,
                 float* __restrict__ out) {
    __shared__ ull s_w2[HIDn*NVn];   // [o][v], broadcast-packed up_w
    __shared__ float s_b[HIDn];
    __shared__ float s_dw[NVn], s_db[NVn];
    for (int i = threadIdx.x; i < HIDn*NVn; i += blockDim.x) {
        float wv = upw[i];
        s_w2[i] = pk2(wv, wv);
    }
    for (int i = threadIdx.x; i < HIDn; i += blockDim.x) s_b[i] = upb[i];
    if (threadIdx.x < NVn) {
        s_dw[threadIdx.x] = dww[threadIdx.x];
        s_db[threadIdx.x] = dwb[threadIdx.x];
    }
    __syncthreads();

    int idx = blockIdx.x * blockDim.x + threadIdx.x;   // pair index
    if (idx >= Bn*(HWn/2)) return;
    int b = idx / (HWn/2);
    int r = (idx - b*(HWn/2)) * 2;     // even pixel index within batch
    int h = r / Wn;
    int w = r - h*Wn;

    float dt = __ldg(dtp);
    float minLat = __ldg(latg);
    float maxLat = __ldg(latg + (size_t)(Hn-1)*Wn);
    float minLon = __ldg(lonp);
    float maxLon = __ldg(lonp + (Wn-1));
    float dLatInv = 1.0f / (maxLat - minLat);
    float dLonInv = 1.0f / (maxLon - minLon);

    float slg = g_slat[h];
    float clg = g_clat[h];
    float lo0 = __ldg(lonp + w);
    float lo1 = __ldg(lonp + w + 1);

    ull yv[NVn];
#pragma unroll
    for (int v = 0; v < NVn; v++) {
        int plane = b*NVn + v;
        size_t base = (size_t)plane*HWn + r;
        float2 up = *reinterpret_cast<const float2*>(U + base);
        float2 vp = *reinterpret_cast<const float2*>(Vf + base);
        const float* pp = g_pad + (size_t)plane*Hpn*Wpn;
        float a0 = sample_one(pp, up.x, vp.x, dt, slg, clg, lo0,
                              minLat, dLatInv, minLon, dLonInv);
        float a1 = sample_one(pp, up.y, vp.y, dt, slg, clg, lo1,
                              minLat, dLatInv, minLon, dLonInv);
        float dwv = s_dw[v], dbv = s_db[v];
        yv[v] = pk2(fmaf(a0, dwv, dbv), fmaf(a1, dwv, dbv));
    }

    float* op = out + (size_t)b*HIDn*HWn + r;
#pragma unroll 8
    for (int o = 0; o < HIDn; o++) {
        ull acc = pk2(s_b[o], s_b[o]);
        const ull* wr = s_w2 + o*NVn;
#pragma unroll
        for (int vq = 0; vq < NVn; vq++) acc = ffma2(yv[vq], wr[vq], acc);
        *reinterpret_cast<ull*>(op + (size_t)o*HWn) = acc;
    }
}

// ---------------------------------------------------------------------------
// Kernel E: pole-row fix on output.
// ---------------------------------------------------------------------------
__global__ void kE_polefix_out(float* __restrict__ out) {
    int bo = blockIdx.x >> 1;
    int which = blockIdx.x & 1;
    float* row = out + (size_t)bo*HWn + (which ? (size_t)(Hn-1)*Wn : 0);

    __shared__ float s[256];
    float sum = 0.f;
    for (int w = threadIdx.x; w < Wn; w += 256) sum += row[w];
    s[threadIdx.x] = sum;
    __syncthreads();
    for (int st = 128; st > 0; st >>= 1) {
        if (threadIdx.x < st) s[threadIdx.x] += s[threadIdx.x + st];
        __syncthreads();
    }
    float mean = s[0] * (1.0f / (float)Wn);
    for (int w = threadIdx.x; w < Wn; w += 256) row[w] = mean;
}

// ---------------------------------------------------------------------------
extern "C" void kernel_launch(void* const* d_in, const int* in_sizes, int n_in,
                              void* d_out, int out_size) {
    const float* hidden = (const float*)d_in[0];
    const float* U      = (const float*)d_in[1];
    const float* V      = (const float*)d_in[2];
    const float* dt     = (const float*)d_in[3];
    const float* latg   = (const float*)d_in[4];
    const float* lonog  = (const float*)d_in[5];
    const float* down_w = (const float*)d_in[6];
    const float* down_b = (const float*)d_in[7];
    const float* dw_w   = (const float*)d_in[8];
    const float* dw_b   = (const float*)d_in[9];
    const float* up_w   = (const float*)d_in[10];
    const float* up_b   = (const float*)d_in[11];
    float* out = (float*)d_out;

    kT_tables<<<2, 256>>>(latg);

    int nPairs = Bn*(HWn/2);                 // 259920
    kA_downproj<<<(nPairs + 255)/256, 256>>>(hidden, down_w, down_b);
    kB_polefix_proj<<<Bn*NVn*2, 256>>>();
    int nHalo = Bn*NVn*HALO_PER_PLANE;       // 138,880
    kC_halo<<<(nHalo + 255)/256, 256>>>();
    kF_sample_upproj<<<(nPairs + 255)/256, 256>>>(U, V, dt, latg, lonog,
                                                  dw_w, dw_b, up_w, up_b, out);
    kE_polefix_out<<<Bn*HIDn*2, 256>>>(out);
}